// round 1
// baseline (speedup 1.0000x reference)
#include <cuda_runtime.h>
#include <cstdint>

// Problem constants
#define BB 32
#define SS 4096
#define DD 512
#define UU 512
#define MROWS (BB * SS)      // 131072

// GEMM tiling
#define MT 128
#define NT 128
#define KT 16
#define NCHUNK (UU / NT)     // 4 u-chunks

// Deterministic scratch (no atomics anywhere)
__device__ float g_decp[BB * UU];            // dec proj + b1 + b2
__device__ float g_pscores[NCHUNK * MROWS];  // partial scores per u-chunk
__device__ float g_scores[MROWS];            // summed scores
__device__ float g_m[BB];
__device__ float g_linv[BB];
__device__ float g_pctx[8 * BB * DD];        // partial context per s-chunk

// ---------------------------------------------------------------------------
// Kernel 0: decoder projection  decp[b][u] = dec[b]@W2[:,u] + b2[u] + b1[u]
// ---------------------------------------------------------------------------
__global__ __launch_bounds__(512) void decp_kernel(
    const float* __restrict__ dec, const float* __restrict__ W2,
    const float* __restrict__ b2, const float* __restrict__ b1)
{
    int b = blockIdx.x;
    int u = threadIdx.x;
    __shared__ float ds[DD];
    ds[u] = dec[b * DD + u];
    __syncthreads();
    float acc = b2[u] + b1[u];
#pragma unroll 8
    for (int d = 0; d < DD; d++)
        acc += ds[d] * W2[d * UU + u];
    g_decp[b * UU + u] = acc;
}

// ---------------------------------------------------------------------------
// Kernel 1: fused GEMM + tanh + dot(V)  -> partial scores
//   block = 128 rows x 128 u's, loops K=512.
//   grid (x = u-chunk[4], y = row-tile[1024]) so same-row blocks are adjacent
//   in bid order (L2 reuse of A rows across u-chunks).
// ---------------------------------------------------------------------------
__global__ __launch_bounds__(256) void gemm_score_kernel(
    const float* __restrict__ A,    // enc [131072, 512]
    const float* __restrict__ W1,   // [512, 512]
    const float* __restrict__ V)    // [512]
{
    __shared__ float As[KT][MT];   // transposed A tile
    __shared__ float Bs[KT][NT];

    const int t  = threadIdx.x;
    const int tx = t & 15;
    const int ty = t >> 4;
    const int rowBase = blockIdx.y * MT;
    const int uBase   = blockIdx.x * NT;
    const int b       = rowBase >> 12;   // rowBase / 4096 (tiles never cross b)

    float acc[8][8];
#pragma unroll
    for (int i = 0; i < 8; i++)
#pragma unroll
        for (int j = 0; j < 8; j++) acc[i][j] = 0.0f;

    // load-index decomposition
    const int arow = t >> 2;   // 0..63
    const int ac4  = t & 3;    // which float4 of the 16 k-cols
    const int brow = t >> 5;   // 0..7
    const int bc4  = t & 31;

    const float* Aptr = A + (size_t)rowBase * DD;
    const float* Bptr = W1 + uBase;

    for (int k0 = 0; k0 < DD; k0 += KT) {
        // A tile: 128 rows x 16 cols, store transposed
#pragma unroll
        for (int l = 0; l < 2; l++) {
            int row = arow + l * 64;
            float4 v = *(const float4*)(Aptr + (size_t)row * DD + k0 + ac4 * 4);
            As[ac4 * 4 + 0][row] = v.x;
            As[ac4 * 4 + 1][row] = v.y;
            As[ac4 * 4 + 2][row] = v.z;
            As[ac4 * 4 + 3][row] = v.w;
        }
        // B tile: W1 rows k0..k0+15, cols uBase..uBase+127
#pragma unroll
        for (int l = 0; l < 2; l++) {
            int row = brow + l * 8;
            float4 v = *(const float4*)(Bptr + (size_t)(k0 + row) * UU + bc4 * 4);
            *(float4*)(&Bs[row][bc4 * 4]) = v;
        }
        __syncthreads();

#pragma unroll
        for (int kk = 0; kk < KT; kk++) {
            float4 a0 = *(const float4*)(&As[kk][ty * 8]);
            float4 a1 = *(const float4*)(&As[kk][ty * 8 + 4]);
            float4 c0 = *(const float4*)(&Bs[kk][tx * 8]);
            float4 c1 = *(const float4*)(&Bs[kk][tx * 8 + 4]);
            float av[8] = {a0.x, a0.y, a0.z, a0.w, a1.x, a1.y, a1.z, a1.w};
            float bvv[8] = {c0.x, c0.y, c0.z, c0.w, c1.x, c1.y, c1.z, c1.w};
#pragma unroll
            for (int i = 0; i < 8; i++)
#pragma unroll
                for (int j = 0; j < 8; j++)
                    acc[i][j] += av[i] * bvv[j];
        }
        __syncthreads();
    }

    // Epilogue: tanh(enc_p + dec_p) * V, reduce over the 128 u's of this block
    float dv[8], vv[8];
#pragma unroll
    for (int j = 0; j < 8; j++) {
        int u = uBase + tx * 8 + j;
        dv[j] = g_decp[b * UU + u];
        vv[j] = __ldg(&V[u]);
    }
#pragma unroll
    for (int i = 0; i < 8; i++) {
        float p = 0.0f;
#pragma unroll
        for (int j = 0; j < 8; j++)
            p += tanhf(acc[i][j] + dv[j]) * vv[j];
        // reduce across the 16 threads (lanes) sharing this row
        p += __shfl_xor_sync(0xffffffffu, p, 8);
        p += __shfl_xor_sync(0xffffffffu, p, 4);
        p += __shfl_xor_sync(0xffffffffu, p, 2);
        p += __shfl_xor_sync(0xffffffffu, p, 1);
        if (tx == 0)
            g_pscores[blockIdx.x * MROWS + rowBase + ty * 8 + i] = p;
    }
}

// ---------------------------------------------------------------------------
// Kernel 2: sum partial scores, per-batch softmax stats (max, 1/sum)
// ---------------------------------------------------------------------------
__global__ __launch_bounds__(256) void stats_kernel()
{
    int b = blockIdx.x;
    int t = threadIdx.x;
    __shared__ float red[256];

    float sv[16];
    float m = -3.0e38f;
#pragma unroll
    for (int i = 0; i < 16; i++) {
        int r = b * SS + t + i * 256;
        float v = g_pscores[r] + g_pscores[MROWS + r] +
                  g_pscores[2 * MROWS + r] + g_pscores[3 * MROWS + r];
        sv[i] = v;
        g_scores[r] = v;
        m = fmaxf(m, v);
    }
    red[t] = m;
    __syncthreads();
    for (int o = 128; o > 0; o >>= 1) {
        if (t < o) red[t] = fmaxf(red[t], red[t + o]);
        __syncthreads();
    }
    float M = red[0];
    __syncthreads();

    float l = 0.0f;
#pragma unroll
    for (int i = 0; i < 16; i++)
        l += expf(sv[i] - M);
    red[t] = l;
    __syncthreads();
    for (int o = 128; o > 0; o >>= 1) {
        if (t < o) red[t] += red[t + o];
        __syncthreads();
    }
    if (t == 0) {
        g_m[b] = M;
        g_linv[b] = 1.0f / red[0];
    }
}

// ---------------------------------------------------------------------------
// Kernel 3: attention weights + partial context
//   grid (x = j-chunk[4], y = s-chunk[8], z = b[32]); 128 threads = 128 j's.
// ---------------------------------------------------------------------------
__global__ __launch_bounds__(128) void context_kernel(
    const float* __restrict__ enc, float* __restrict__ out_w)
{
    int b = blockIdx.z;
    int sBase = blockIdx.y * 512;
    int jc = blockIdx.x;
    int t = threadIdx.x;

    __shared__ float ws[512];
    float m = g_m[b], linv = g_linv[b];
    for (int k = t; k < 512; k += 128) {
        float w = expf(g_scores[b * SS + sBase + k] - m) * linv;
        ws[k] = w;
        if (jc == 0) out_w[b * SS + sBase + k] = w;
    }
    __syncthreads();

    int j = jc * 128 + t;
    const float* ep = enc + ((size_t)(b * SS + sBase)) * DD + j;
    float a0 = 0.f, a1 = 0.f, a2 = 0.f, a3 = 0.f;
#pragma unroll 2
    for (int s = 0; s < 512; s += 4) {
        a0 += ws[s + 0] * __ldg(ep + (size_t)(s + 0) * DD);
        a1 += ws[s + 1] * __ldg(ep + (size_t)(s + 1) * DD);
        a2 += ws[s + 2] * __ldg(ep + (size_t)(s + 2) * DD);
        a3 += ws[s + 3] * __ldg(ep + (size_t)(s + 3) * DD);
    }
    g_pctx[(blockIdx.y * BB + b) * DD + j] = (a0 + a1) + (a2 + a3);
}

// ---------------------------------------------------------------------------
// Kernel 4: reduce partial contexts -> out[0:16384]
// ---------------------------------------------------------------------------
__global__ __launch_bounds__(256) void ctx_reduce_kernel(float* __restrict__ out_ctx)
{
    int i = blockIdx.x * 256 + threadIdx.x;   // 0..16383
    if (i < BB * DD) {
        float s = 0.0f;
#pragma unroll
        for (int y = 0; y < 8; y++)
            s += g_pctx[y * (BB * DD) + i];
        out_ctx[i] = s;
    }
}

// ---------------------------------------------------------------------------
extern "C" void kernel_launch(void* const* d_in, const int* in_sizes, int n_in,
                              void* d_out, int out_size)
{
    const float* enc = (const float*)d_in[0];  // [32,4096,512]
    const float* dec = (const float*)d_in[1];  // [32,512]
    const float* W1  = (const float*)d_in[2];  // [512,512]
    const float* b1  = (const float*)d_in[3];  // [512]
    const float* W2  = (const float*)d_in[4];  // [512,512]
    const float* b2  = (const float*)d_in[5];  // [512]
    const float* V   = (const float*)d_in[6];  // [512,1]
    // bv = d_in[7]: softmax is shift-invariant, bv cancels exactly.

    float* out     = (float*)d_out;
    float* out_ctx = out;              // [32*512]
    float* out_w   = out + BB * DD;    // [32*4096]

    decp_kernel<<<BB, 512>>>(dec, W2, b2, b1);
    gemm_score_kernel<<<dim3(NCHUNK, MROWS / MT), 256>>>(enc, W1, V);
    stats_kernel<<<BB, 256>>>();
    context_kernel<<<dim3(4, 8, BB), 128>>>(enc, out_w);
    ctx_reduce_kernel<<<(BB * DD + 255) / 256, 256>>>(out_ctx);
}

// round 5
// speedup vs baseline: 1.8059x; 1.8059x over previous
#include <cuda_runtime.h>
#include <cuda_bf16.h>
#include <cstdint>

// Problem constants
#define BB 32
#define SS 4096
#define DD 512
#define UU 512
#define MROWS (BB * SS)      // 131072
#define NCHUNK 4             // 4 u-tiles of 128

// GEMM smem layout (per stage: Ah|Al|Bh|Bl, each 128 rows x 80 bytes)
#define PLANE_BYTES (128 * 80)            // 10240
#define STAGE_BYTES (4 * PLANE_BYTES)     // 40960
#define OFF_AH(s) ((s) * STAGE_BYTES)
#define OFF_AL(s) ((s) * STAGE_BYTES + PLANE_BYTES)
#define OFF_BH(s) ((s) * STAGE_BYTES + 2 * PLANE_BYTES)
#define OFF_BL(s) ((s) * STAGE_BYTES + 3 * PLANE_BYTES)
#define OFF_SCRATCH (2 * STAGE_BYTES)     // 81920
#define SMEM_TOTAL (2 * STAGE_BYTES + 512)

// Deterministic scratch
__device__ __nv_bfloat16 g_w1bf[2 * UU * DD];   // [plane][u][k], 1 MB
__device__ float g_decp[BB * UU];
__device__ float g_pscores[NCHUNK * MROWS];
__device__ float g_scores[MROWS];
__device__ float g_m[BB];
__device__ float g_linv[BB];
__device__ float g_pctx[8 * BB * DD];

// ---------------------------------------------------------------------------
// Helpers (sm_80-era PTX only: ldmatrix / cp.async / mma.sync)
// ---------------------------------------------------------------------------
__device__ __forceinline__ uint32_t smem_u32(const void* p) {
    uint32_t a;
    asm("{ .reg .u64 t; cvta.to.shared.u64 t, %1; cvt.u32.u64 %0, t; }" : "=r"(a) : "l"(p));
    return a;
}
__device__ __forceinline__ void cp_async16(uint32_t dst, const void* src) {
    asm volatile("cp.async.cg.shared.global [%0], [%1], 16;" :: "r"(dst), "l"(src) : "memory");
}
#define CP_COMMIT() asm volatile("cp.async.commit_group;" ::: "memory")
#define CP_WAIT0()  asm volatile("cp.async.wait_group 0;" ::: "memory")

__device__ __forceinline__ void ldm_x4(uint32_t& r0, uint32_t& r1, uint32_t& r2, uint32_t& r3,
                                       uint32_t addr) {
    asm volatile("ldmatrix.sync.aligned.m8n8.x4.shared.b16 {%0,%1,%2,%3}, [%4];"
                 : "=r"(r0), "=r"(r1), "=r"(r2), "=r"(r3) : "r"(addr));
}
__device__ __forceinline__ void mma_bf16(float* c, const uint32_t* a, uint32_t b0, uint32_t b1) {
    asm volatile(
        "mma.sync.aligned.m16n8k16.row.col.f32.bf16.bf16.f32 "
        "{%0,%1,%2,%3}, {%4,%5,%6,%7}, {%8,%9}, {%0,%1,%2,%3};"
        : "+f"(c[0]), "+f"(c[1]), "+f"(c[2]), "+f"(c[3])
        : "r"(a[0]), "r"(a[1]), "r"(a[2]), "r"(a[3]), "r"(b0), "r"(b1));
}
__device__ __forceinline__ ushort bf16_hi(float x, float& res) {
    __nv_bfloat16 h = __float2bfloat16_rn(x);
    res = x - __bfloat162float(h);
    return __bfloat16_as_ushort(h);
}

// ---------------------------------------------------------------------------
// Kernel P: split W1 into transposed bf16 planes  g_w1bf[plane][u][k]
// ---------------------------------------------------------------------------
__global__ __launch_bounds__(256) void w1_prep_kernel(const float* __restrict__ W1)
{
    int idx = blockIdx.x * 256 + threadIdx.x;   // 0..262143
    int kp = idx & 255;            // k pair
    int u = (idx >> 8) & 511;
    int plane = idx >> 17;
    int k = kp * 2;

    float w0 = W1[(size_t)k * UU + u];
    float w1v = W1[(size_t)(k + 1) * UU + u];
    float r0, r1;
    ushort h0 = bf16_hi(w0, r0);
    ushort h1 = bf16_hi(w1v, r1);
    ushort x0, x1;
    if (plane == 0) { x0 = h0; x1 = h1; }
    else {
        float t;
        x0 = bf16_hi(r0, t);
        x1 = bf16_hi(r1, t);
    }
    ((uint32_t*)g_w1bf)[(plane * (UU * DD) + u * DD + k) >> 1] =
        (uint32_t)x0 | ((uint32_t)x1 << 16);
}

// ---------------------------------------------------------------------------
// Kernel 0: decoder projection  decp[b][u] = dec[b]@W2[:,u] + b2[u] + b1[u]
// ---------------------------------------------------------------------------
__global__ __launch_bounds__(512) void decp_kernel(
    const float* __restrict__ dec, const float* __restrict__ W2,
    const float* __restrict__ b2, const float* __restrict__ b1)
{
    int b = blockIdx.x;
    int u = threadIdx.x;
    __shared__ float ds[DD];
    ds[u] = dec[b * DD + u];
    __syncthreads();
    float acc = b2[u] + b1[u];
#pragma unroll 8
    for (int d = 0; d < DD; d++)
        acc += ds[d] * W2[d * UU + u];
    g_decp[b * UU + u] = acc;
}

// ---------------------------------------------------------------------------
// Kernel 1: mma.sync bf16 3-pass GEMM + fused tanh·V epilogue
//   CTA 128 rows x 128 u. 8 warps = 4(m) x 2(n); warp tile 32m x 64n.
//   K = 512 in 16 chunks of 32; double-buffered smem pipeline.
// ---------------------------------------------------------------------------
__global__ __launch_bounds__(256) void gemm_score_mma(
    const float* __restrict__ enc, const float* __restrict__ V)
{
    extern __shared__ char smem[];
    const uint32_t sb = smem_u32(smem);
    const int tid = threadIdx.x;
    const int lane = tid & 31;
    const int wid = tid >> 5;
    const int warpM = wid & 3;
    const int warpN = wid >> 2;
    const int nBase = blockIdx.x * 128;
    const int rowBase = blockIdx.y * 128;
    const int b = rowBase >> 12;

    // ldmatrix per-lane index decomposition
    const int amrow = lane & 15;
    const int akoff = ((lane >> 4) & 1) * 8;
    const int bnidx = (lane & 7) + ((lane >> 4) & 1) * 8;
    const int bkidx = ((lane >> 3) & 1) * 8;

    float c[2][8][4];
#pragma unroll
    for (int mi = 0; mi < 2; mi++)
#pragma unroll
        for (int ni = 0; ni < 8; ni++)
#pragma unroll
            for (int q = 0; q < 4; q++) c[mi][ni][q] = 0.0f;

    const float* Aptr = enc + (size_t)rowBase * DD;

    // --- pipeline lambdas (expressed as macros via plain code) ---
    float4 av[4];

#define LOAD_B(cc, s)                                                                   \
    {                                                                                   \
        _Pragma("unroll")                                                               \
        for (int i = 0; i < 4; i++) {                                                   \
            int id = tid + 256 * i;                                                     \
            int plane = id >> 9;                                                        \
            int n = (id >> 2) & 127;                                                    \
            int ch = id & 3;                                                            \
            const __nv_bfloat16* src = g_w1bf + (size_t)plane * (UU * DD) +             \
                                       (size_t)(nBase + n) * DD + (cc) * 32 + ch * 8;   \
            uint32_t dst = sb + (plane ? OFF_BL(s) : OFF_BH(s)) + n * 80 + ch * 16;     \
            cp_async16(dst, src);                                                       \
        }                                                                               \
        CP_COMMIT();                                                                    \
    }

#define LOAD_A_REGS(cc)                                                                 \
    {                                                                                   \
        _Pragma("unroll")                                                               \
        for (int i = 0; i < 4; i++) {                                                   \
            int id = tid + 256 * i;                                                     \
            int row = id >> 3;                                                          \
            int f4 = id & 7;                                                            \
            av[i] = *(const float4*)(Aptr + (size_t)row * DD + (cc) * 32 + f4 * 4);     \
        }                                                                               \
    }

#define STS_A(s)                                                                        \
    {                                                                                   \
        _Pragma("unroll")                                                               \
        for (int i = 0; i < 4; i++) {                                                   \
            int id = tid + 256 * i;                                                     \
            int row = id >> 3;                                                          \
            int f4 = id & 7;                                                            \
            float r0, r1, r2, r3, t;                                                    \
            ushort h0 = bf16_hi(av[i].x, r0), h1 = bf16_hi(av[i].y, r1);                \
            ushort h2 = bf16_hi(av[i].z, r2), h3 = bf16_hi(av[i].w, r3);                \
            ushort l0 = bf16_hi(r0, t), l1 = bf16_hi(r1, t);                            \
            ushort l2 = bf16_hi(r2, t), l3 = bf16_hi(r3, t);                            \
            *(uint2*)(smem + OFF_AH(s) + row * 80 + f4 * 8) =                           \
                make_uint2((uint32_t)h0 | ((uint32_t)h1 << 16),                         \
                           (uint32_t)h2 | ((uint32_t)h3 << 16));                        \
            *(uint2*)(smem + OFF_AL(s) + row * 80 + f4 * 8) =                           \
                make_uint2((uint32_t)l0 | ((uint32_t)l1 << 16),                         \
                           (uint32_t)l2 | ((uint32_t)l3 << 16));                        \
        }                                                                               \
    }

#define COMPUTE(s)                                                                      \
    {                                                                                   \
        _Pragma("unroll")                                                               \
        for (int p = 0; p < 3; p++) {                                                   \
            uint32_t aoff = (p == 2) ? OFF_AL(s) : OFF_AH(s);                           \
            uint32_t boff = (p == 1) ? OFF_BL(s) : OFF_BH(s);                           \
            _Pragma("unroll")                                                           \
            for (int kk = 0; kk < 2; kk++) {                                            \
                uint32_t af[2][4];                                                      \
                _Pragma("unroll")                                                       \
                for (int mi = 0; mi < 2; mi++)                                          \
                    ldm_x4(af[mi][0], af[mi][1], af[mi][2], af[mi][3],                  \
                           sb + aoff + (warpM * 32 + mi * 16 + amrow) * 80 +            \
                               (kk * 16 + akoff) * 2);                                  \
                uint32_t bf[4][4];                                                      \
                _Pragma("unroll")                                                       \
                for (int j = 0; j < 4; j++)                                             \
                    ldm_x4(bf[j][0], bf[j][1], bf[j][2], bf[j][3],                      \
                           sb + boff + (warpN * 64 + j * 16 + bnidx) * 80 +             \
                               (kk * 16 + bkidx) * 2);                                  \
                _Pragma("unroll")                                                       \
                for (int mi = 0; mi < 2; mi++)                                          \
                    _Pragma("unroll")                                                   \
                    for (int j = 0; j < 4; j++) {                                       \
                        mma_bf16(c[mi][2 * j], af[mi], bf[j][0], bf[j][1]);             \
                        mma_bf16(c[mi][2 * j + 1], af[mi], bf[j][2], bf[j][3]);         \
                    }                                                                   \
            }                                                                           \
        }                                                                               \
    }

    // prologue: stage 0
    LOAD_B(0, 0);
    LOAD_A_REGS(0);
    STS_A(0);
    CP_WAIT0();
    __syncthreads();

#pragma unroll 1
    for (int cc = 0; cc < 16; cc++) {
        int s = cc & 1;
        if (cc < 15) {
            LOAD_B(cc + 1, s ^ 1);
            LOAD_A_REGS(cc + 1);
        }
        COMPUTE(s);
        if (cc < 15) {
            STS_A(s ^ 1);
            CP_WAIT0();
            __syncthreads();
        }
    }

    // ---------------- Epilogue: tanh(p + decp) * V, reduce over this CTA's 128 u
    float dv[16], vv[16];
#pragma unroll
    for (int ni = 0; ni < 8; ni++)
#pragma unroll
        for (int h = 0; h < 2; h++) {
            int u = nBase + warpN * 64 + ni * 8 + (lane & 3) * 2 + h;
            dv[ni * 2 + h] = __ldg(&g_decp[b * UU + u]);
            vv[ni * 2 + h] = __ldg(&V[u]);
        }

    float sA[2], sB[2];
#pragma unroll
    for (int mi = 0; mi < 2; mi++) {
        float s0 = 0.0f, s1 = 0.0f;
#pragma unroll
        for (int ni = 0; ni < 8; ni++) {
#pragma unroll
            for (int h = 0; h < 2; h++) {
                s0 += tanhf(c[mi][ni][h] + dv[ni * 2 + h]) * vv[ni * 2 + h];
                s1 += tanhf(c[mi][ni][2 + h] + dv[ni * 2 + h]) * vv[ni * 2 + h];
            }
        }
        s0 += __shfl_xor_sync(0xffffffffu, s0, 1);
        s0 += __shfl_xor_sync(0xffffffffu, s0, 2);
        s1 += __shfl_xor_sync(0xffffffffu, s1, 1);
        s1 += __shfl_xor_sync(0xffffffffu, s1, 2);
        sA[mi] = s0;
        sB[mi] = s1;
    }

    float* scratch = (float*)(smem + OFF_SCRATCH);
    __syncthreads();   // mainloop smem reads done before (harmless) reuse
    if (warpN == 1 && (lane & 3) == 0) {
#pragma unroll
        for (int mi = 0; mi < 2; mi++) {
            int r0 = warpM * 32 + mi * 16 + (lane >> 2);
            scratch[r0] = sA[mi];
            scratch[r0 + 8] = sB[mi];
        }
    }
    __syncthreads();
    if (warpN == 0 && (lane & 3) == 0) {
#pragma unroll
        for (int mi = 0; mi < 2; mi++) {
            int r0 = warpM * 32 + mi * 16 + (lane >> 2);
            g_pscores[(size_t)blockIdx.x * MROWS + rowBase + r0] = sA[mi] + scratch[r0];
            g_pscores[(size_t)blockIdx.x * MROWS + rowBase + r0 + 8] = sB[mi] + scratch[r0 + 8];
        }
    }
}

// ---------------------------------------------------------------------------
// Kernel 2: sum 4 partial-score planes, per-batch softmax stats
// ---------------------------------------------------------------------------
__global__ __launch_bounds__(256) void stats_kernel()
{
    int b = blockIdx.x;
    int t = threadIdx.x;
    __shared__ float red[256];

    float sv[16];
    float m = -3.0e38f;
#pragma unroll
    for (int i = 0; i < 16; i++) {
        int r = b * SS + t + i * 256;
        float v = g_pscores[r] + g_pscores[MROWS + r] +
                  g_pscores[2 * MROWS + r] + g_pscores[3 * MROWS + r];
        sv[i] = v;
        g_scores[r] = v;
        m = fmaxf(m, v);
    }
    red[t] = m;
    __syncthreads();
    for (int o = 128; o > 0; o >>= 1) {
        if (t < o) red[t] = fmaxf(red[t], red[t + o]);
        __syncthreads();
    }
    float M = red[0];
    __syncthreads();

    float l = 0.0f;
#pragma unroll
    for (int i = 0; i < 16; i++)
        l += expf(sv[i] - M);
    red[t] = l;
    __syncthreads();
    for (int o = 128; o > 0; o >>= 1) {
        if (t < o) red[t] += red[t + o];
        __syncthreads();
    }
    if (t == 0) {
        g_m[b] = M;
        g_linv[b] = 1.0f / red[0];
    }
}

// ---------------------------------------------------------------------------
// Kernel 3: attention weights + partial context
// ---------------------------------------------------------------------------
__global__ __launch_bounds__(128) void context_kernel(
    const float* __restrict__ enc, float* __restrict__ out_w)
{
    int b = blockIdx.z;
    int sBase = blockIdx.y * 512;
    int jc = blockIdx.x;
    int t = threadIdx.x;

    __shared__ float ws[512];
    float m = g_m[b], linv = g_linv[b];
    for (int k = t; k < 512; k += 128) {
        float w = expf(g_scores[b * SS + sBase + k] - m) * linv;
        ws[k] = w;
        if (jc == 0) out_w[b * SS + sBase + k] = w;
    }
    __syncthreads();

    int j = jc * 128 + t;
    const float* ep = enc + ((size_t)(b * SS + sBase)) * DD + j;
    float a0 = 0.f, a1 = 0.f, a2 = 0.f, a3 = 0.f;
#pragma unroll 2
    for (int s = 0; s < 512; s += 4) {
        a0 += ws[s + 0] * __ldg(ep + (size_t)(s + 0) * DD);
        a1 += ws[s + 1] * __ldg(ep + (size_t)(s + 1) * DD);
        a2 += ws[s + 2] * __ldg(ep + (size_t)(s + 2) * DD);
        a3 += ws[s + 3] * __ldg(ep + (size_t)(s + 3) * DD);
    }
    g_pctx[(blockIdx.y * BB + b) * DD + j] = (a0 + a1) + (a2 + a3);
}

// ---------------------------------------------------------------------------
// Kernel 4: reduce partial contexts
// ---------------------------------------------------------------------------
__global__ __launch_bounds__(256) void ctx_reduce_kernel(float* __restrict__ out_ctx)
{
    int i = blockIdx.x * 256 + threadIdx.x;
    if (i < BB * DD) {
        float s = 0.0f;
#pragma unroll
        for (int y = 0; y < 8; y++)
            s += g_pctx[y * (BB * DD) + i];
        out_ctx[i] = s;
    }
}

// ---------------------------------------------------------------------------
extern "C" void kernel_launch(void* const* d_in, const int* in_sizes, int n_in,
                              void* d_out, int out_size)
{
    const float* enc = (const float*)d_in[0];
    const float* dec = (const float*)d_in[1];
    const float* W1  = (const float*)d_in[2];
    const float* b1  = (const float*)d_in[3];
    const float* W2  = (const float*)d_in[4];
    const float* b2  = (const float*)d_in[5];
    const float* V   = (const float*)d_in[6];
    // bv cancels in softmax.

    float* out     = (float*)d_out;
    float* out_ctx = out;
    float* out_w   = out + BB * DD;

    cudaFuncSetAttribute(gemm_score_mma, cudaFuncAttributeMaxDynamicSharedMemorySize, SMEM_TOTAL);

    w1_prep_kernel<<<1024, 256>>>(W1);
    decp_kernel<<<BB, 512>>>(dec, W2, b2, b1);
    gemm_score_mma<<<dim3(NCHUNK, MROWS / 128), 256, SMEM_TOTAL>>>(enc, V);
    stats_kernel<<<BB, 256>>>();
    context_kernel<<<dim3(4, 8, BB), 128>>>(enc, out_w);
    ctx_reduce_kernel<<<(BB * DD + 255) / 256, 256>>>(out_ctx);
}